// round 16
// baseline (speedup 1.0000x reference)
#include <cuda_runtime.h>
#include <cuda_fp16.h>
#include <math.h>

#define NMAX 100000
#define EMAX 1600000
#define FIN  128
#define HID  64
#define ELLCAP 64

// ---------------- scratch (device globals: no allocation allowed) ----------
__device__ __half2  g_gh [NMAX * 32];   // layer-1 messages (dinv-prescaled after k_scale)
__device__ __half2  g_gh2[NMAX * 32];   // layer-2 messages (dinv-prescaled)
__device__ unsigned g_ahi[NMAX * 32];   // agg1 out, f16 (GEMM2 A)
__device__ float    g_dinv[NMAX];
__device__ int      g_cnt[NMAX];
__device__ int      g_ell[(size_t)NMAX * ELLCAP];   // BYTE OFFSETS (src*128)

// ---------------- helpers ---------------------------------------------------
__device__ __forceinline__ unsigned h2u(__half2 h) {
    return *reinterpret_cast<unsigned*>(&h);
}
__device__ __forceinline__ __half2 u2h(unsigned u) {
    return *reinterpret_cast<__half2*>(&u);
}
__device__ __forceinline__ float2 u2f(unsigned u) {
    return __half22float2(u2h(u));
}

#define MMA16816(c, a0, a1, a2, a3, b0, b1)                                      \
    asm volatile("mma.sync.aligned.m16n8k16.row.col.f32.f16.f16.f32 "            \
                 "{%0,%1,%2,%3},{%4,%5,%6,%7},{%8,%9},{%0,%1,%2,%3};"            \
                 : "+f"(c[0]), "+f"(c[1]), "+f"(c[2]), "+f"(c[3])                \
                 : "r"(a0), "r"(a1), "r"(a2), "r"(a3), "r"(b0), "r"(b1))

// ---------------- mega kernel: ELL scatter 2:1 interleaved with GEMM1 ------
__global__ __launch_bounds__(256) void mega1(
    const float* __restrict__ x, const float* __restrict__ W,
    const int* __restrict__ src, const int* __restrict__ dst,
    int n, int e)
{
    __shared__ unsigned As[128][20];       // A hi plane
    __shared__ unsigned Ws[64][20];        // W hi plane

    const int tid = threadIdx.x;
    const int q = blockIdx.x / 3, r = blockIdx.x % 3;

    if (r < 2) {
        int sidx = 2 * q + r;
        int base = (sidx * 256 + tid) * 4;
        if (base + 4 <= e) {
            int4 d4 = *reinterpret_cast<const int4*>(dst + base);
            int4 s4 = *reinterpret_cast<const int4*>(src + base);
            int p;
            p = atomicAdd(&g_cnt[d4.x], 1); if (p < ELLCAP) g_ell[(size_t)d4.x * ELLCAP + p] = s4.x << 7;
            p = atomicAdd(&g_cnt[d4.y], 1); if (p < ELLCAP) g_ell[(size_t)d4.y * ELLCAP + p] = s4.y << 7;
            p = atomicAdd(&g_cnt[d4.z], 1); if (p < ELLCAP) g_ell[(size_t)d4.z * ELLCAP + p] = s4.z << 7;
            p = atomicAdd(&g_cnt[d4.w], 1); if (p < ELLCAP) g_ell[(size_t)d4.w * ELLCAP + p] = s4.w << 7;
        } else {
            for (int i = base; i < e; i++) {
                int d = dst[i];
                int p = atomicAdd(&g_cnt[d], 1);
                if (p < ELLCAP) g_ell[(size_t)d * ELLCAP + p] = src[i] << 7;
            }
        }
        return;
    }

    // GEMM1: 128x64 tile, single plane (A-hi f16 x W-hi f16)
    const int wid = tid >> 5, lane = tid & 31;
    const int g = lane >> 2, t = lane & 3;
    const int blockRow = q * 128;
    const int wr = wid * 16;

    float c[8][4];
#pragma unroll
    for (int i = 0; i < 8; i++)
#pragma unroll
        for (int j = 0; j < 4; j++) c[i][j] = 0.f;

    for (int kc = 0; kc < FIN; kc += 32) {
        {
            int nn = tid & 63;
            int k2b = (tid >> 6) * 4;
#pragma unroll
            for (int j = 0; j < 4; j++) {
                int k2 = k2b + j;
                float w0 = W[(size_t)(kc + 2 * k2) * 64 + nn];
                float w1 = W[(size_t)(kc + 2 * k2 + 1) * 64 + nn];
                Ws[nn][k2] = h2u(__floats2half2_rn(w0, w1));
            }
        }
        {
            int row = tid >> 1;
            int kh = (tid & 1) * 16;
            int grow = blockRow + row;
#pragma unroll
            for (int j = 0; j < 4; j++) {
                float4 v = make_float4(0.f, 0.f, 0.f, 0.f);
                if (grow < n)
                    v = *reinterpret_cast<const float4*>(x + (size_t)grow * FIN + kc + kh + j * 4);
                int k2 = (kh >> 1) + j * 2;
                As[row][k2]     = h2u(__floats2half2_rn(v.x, v.y));
                As[row][k2 + 1] = h2u(__floats2half2_rn(v.z, v.w));
            }
        }
        __syncthreads();

#pragma unroll
        for (int ks = 0; ks < 2; ks++) {
            const int kb = ks * 8;
            unsigned a0 = As[wr + g][t + kb],     a1 = As[wr + g + 8][t + kb];
            unsigned a2 = As[wr + g][t + 4 + kb], a3 = As[wr + g + 8][t + 4 + kb];
#pragma unroll
            for (int nt = 0; nt < 8; nt++) {
                unsigned b0 = Ws[nt * 8 + g][t + kb], b1 = Ws[nt * 8 + g][t + 4 + kb];
                MMA16816(c[nt], a0, a1, a2, a3, b0, b1);
            }
        }
        __syncthreads();
    }

    int r0 = blockRow + wr + g, r1 = r0 + 8;
#pragma unroll
    for (int nt = 0; nt < 8; nt++) {
        if (r0 < n) g_gh[r0 * 32 + nt * 4 + t] = __floats2half2_rn(c[nt][0], c[nt][1]);
        if (r1 < n) g_gh[r1 * 32 + nt * 4 + t] = __floats2half2_rn(c[nt][2], c[nt][3]);
    }
}

// ---------------- k_scale: dinv = rsqrt(cnt+1); g_gh *= dinv[row] ----------
__global__ __launch_bounds__(256) void k_scale(int n) {
    int i = blockIdx.x * 256 + threadIdx.x;      // uint2 index
    if (i >= n * 16) return;
    int row = i >> 4;
    float dv = rsqrtf((float)g_cnt[row] + 1.0f);
    if ((i & 15) == 0) g_dinv[row] = dv;
    __half2* p = g_gh + 2 * i;
    float2 f0 = __half22float2(p[0]);
    float2 f1 = __half22float2(p[1]);
    p[0] = __floats2half2_rn(f0.x * dv, f0.y * dv);
    p[1] = __floats2half2_rn(f1.x * dv, f1.y * dv);
}

// ---------------- gather: quarter-warp LDG.128 streams ---------------------
// Lane l: qtr = l>>3 (edge stream 0..3), og = l&7 (16B group = cols 8og..8og+7).
// acc[0..3] = float2 sums of the 4 half2 components. Self-loop & tails gated
// to qtr 0; caller combines quarters via shfl.xor(8) then (16).
__device__ __forceinline__ void gather128(
    const char* __restrict__ ghb, int w, int qtr, int og, int lane,
    float2 acc[4])
{
    const char* basep = ghb + og * 16;
#pragma unroll
    for (int c = 0; c < 4; c++) acc[c] = make_float2(0.f, 0.f);
    if (qtr == 0) {                          // self-loop once
        uint4 v = *reinterpret_cast<const uint4*>(basep + ((size_t)w << 7));
        acc[0] = u2f(v.x); acc[1] = u2f(v.y); acc[2] = u2f(v.z); acc[3] = u2f(v.w);
    }

    int m = __ldg(&g_cnt[w]); if (m > ELLCAP) m = ELLCAP;
    const int* row = g_ell + (size_t)w * ELLCAP;
    int myoff = (lane < m) ? row[lane] : 0;

    if (m > 32) {                            // rare tail, qtr 0 only
        if (qtr == 0) {
            for (int j = 32; j < m; j++) {
                uint4 v = *reinterpret_cast<const uint4*>(basep + (unsigned)__ldg(&row[j]));
                float2 f0 = u2f(v.x), f1 = u2f(v.y), f2 = u2f(v.z), f3 = u2f(v.w);
                acc[0].x += f0.x; acc[0].y += f0.y;
                acc[1].x += f1.x; acc[1].y += f1.y;
                acc[2].x += f2.x; acc[2].y += f2.y;
                acc[3].x += f3.x; acc[3].y += f3.y;
            }
        }
        m = 32;
    }

    int j = 0;
    // 16 edges per round: 4 per stream, depth-2 f16 trees per component
    for (; j + 16 <= m; j += 16) {
        int s[4];
#pragma unroll
        for (int q = 0; q < 4; q++) s[q] = __shfl_sync(0xffffffffu, myoff, j + 4 * q + qtr);
        uint4 v[4];
#pragma unroll
        for (int q = 0; q < 4; q++) v[q] = *reinterpret_cast<const uint4*>(basep + (unsigned)s[q]);
        __half2 tx = __hadd2(__hadd2(u2h(v[0].x), u2h(v[1].x)), __hadd2(u2h(v[2].x), u2h(v[3].x)));
        __half2 ty = __hadd2(__hadd2(u2h(v[0].y), u2h(v[1].y)), __hadd2(u2h(v[2].y), u2h(v[3].y)));
        __half2 tz = __hadd2(__hadd2(u2h(v[0].z), u2h(v[1].z)), __hadd2(u2h(v[2].z), u2h(v[3].z)));
        __half2 tw = __hadd2(__hadd2(u2h(v[0].w), u2h(v[1].w)), __hadd2(u2h(v[2].w), u2h(v[3].w)));
        float2 fx = __half22float2(tx), fy = __half22float2(ty);
        float2 fz = __half22float2(tz), fw = __half22float2(tw);
        acc[0].x += fx.x; acc[0].y += fx.y;
        acc[1].x += fy.x; acc[1].y += fy.y;
        acc[2].x += fz.x; acc[2].y += fz.y;
        acc[3].x += fw.x; acc[3].y += fw.y;
    }
    // 8 edges: 2 per stream
    if (j + 8 <= m) {
        int s0 = __shfl_sync(0xffffffffu, myoff, j + qtr);
        int s1 = __shfl_sync(0xffffffffu, myoff, j + 4 + qtr);
        uint4 v0 = *reinterpret_cast<const uint4*>(basep + (unsigned)s0);
        uint4 v1 = *reinterpret_cast<const uint4*>(basep + (unsigned)s1);
        float2 fx = __half22float2(__hadd2(u2h(v0.x), u2h(v1.x)));
        float2 fy = __half22float2(__hadd2(u2h(v0.y), u2h(v1.y)));
        float2 fz = __half22float2(__hadd2(u2h(v0.z), u2h(v1.z)));
        float2 fw = __half22float2(__hadd2(u2h(v0.w), u2h(v1.w)));
        acc[0].x += fx.x; acc[0].y += fx.y;
        acc[1].x += fy.x; acc[1].y += fy.y;
        acc[2].x += fz.x; acc[2].y += fz.y;
        acc[3].x += fw.x; acc[3].y += fw.y;
        j += 8;
    }
    // 4 edges: 1 per stream
    if (j + 4 <= m) {
        int s = __shfl_sync(0xffffffffu, myoff, j + qtr);
        uint4 v = *reinterpret_cast<const uint4*>(basep + (unsigned)s);
        float2 f0 = u2f(v.x), f1 = u2f(v.y), f2 = u2f(v.z), f3 = u2f(v.w);
        acc[0].x += f0.x; acc[0].y += f0.y;
        acc[1].x += f1.x; acc[1].y += f1.y;
        acc[2].x += f2.x; acc[2].y += f2.y;
        acc[3].x += f3.x; acc[3].y += f3.y;
        j += 4;
    }
    // remaining 1..3 edges: streams qtr < rem take one each
    int rem = m - j;
    if (rem > 0) {
        int idx = j + ((qtr < rem) ? qtr : 0);
        int s = __shfl_sync(0xffffffffu, myoff, idx);
        if (qtr < rem) {
            uint4 v = *reinterpret_cast<const uint4*>(basep + (unsigned)s);
            float2 f0 = u2f(v.x), f1 = u2f(v.y), f2 = u2f(v.z), f3 = u2f(v.w);
            acc[0].x += f0.x; acc[0].y += f0.y;
            acc[1].x += f1.x; acc[1].y += f1.y;
            acc[2].x += f2.x; acc[2].y += f2.y;
            acc[3].x += f3.x; acc[3].y += f3.y;
        }
    }
}

// ---------------- aggregation: one warp per node ----------------------------
template <int LAYER, bool FINAL>
__global__ __launch_bounds__(256) void agg_kernel(
    const float* __restrict__ bias, const float* __restrict__ Wc,
    const float* __restrict__ bc, float* __restrict__ out, int n)
{
    const char* __restrict__ ghb =
        reinterpret_cast<const char*>(LAYER == 1 ? g_gh : g_gh2);

    int w = (int)((blockIdx.x * 256 + threadIdx.x) >> 5);
    int l = threadIdx.x & 31;
    if (w >= n) return;
    const int qtr = l >> 3, og = l & 7;

    float2 acc[4];
    gather128(ghb, w, qtr, og, l, acc);

    // combine quarter streams: lanes og, og+8, og+16, og+24 share og
#pragma unroll
    for (int c = 0; c < 4; c++) {
        acc[c].x += __shfl_xor_sync(0xffffffffu, acc[c].x, 8);
        acc[c].y += __shfl_xor_sync(0xffffffffu, acc[c].y, 8);
        acc[c].x += __shfl_xor_sync(0xffffffffu, acc[c].x, 16);
        acc[c].y += __shfl_xor_sync(0xffffffffu, acc[c].y, 16);
    }

    float dv = g_dinv[w];
    float4 bb0 = reinterpret_cast<const float4*>(bias)[2 * og];
    float4 bb1 = reinterpret_cast<const float4*>(bias)[2 * og + 1];
    float v0 = fmaxf(fmaf(dv, acc[0].x, bb0.x), 0.f);
    float v1 = fmaxf(fmaf(dv, acc[0].y, bb0.y), 0.f);
    float v2 = fmaxf(fmaf(dv, acc[1].x, bb0.z), 0.f);
    float v3 = fmaxf(fmaf(dv, acc[1].y, bb0.w), 0.f);
    float v4 = fmaxf(fmaf(dv, acc[2].x, bb1.x), 0.f);
    float v5 = fmaxf(fmaf(dv, acc[2].y, bb1.y), 0.f);
    float v6 = fmaxf(fmaf(dv, acc[3].x, bb1.z), 0.f);
    float v7 = fmaxf(fmaf(dv, acc[3].y, bb1.w), 0.f);

    if (FINAL) {
        float4 wc0 = reinterpret_cast<const float4*>(Wc)[2 * og];
        float4 wc1 = reinterpret_cast<const float4*>(Wc)[2 * og + 1];
        float p = fmaf(v0, wc0.x, fmaf(v1, wc0.y, fmaf(v2, wc0.z, v3 * wc0.w)));
        p = fmaf(v4, wc1.x, fmaf(v5, wc1.y, fmaf(v6, wc1.z, fmaf(v7, wc1.w, p))));
#pragma unroll
        for (int off = 4; off; off >>= 1) p += __shfl_xor_sync(0xffffffffu, p, off);
        if (l == 0) out[w] = p + bc[0];
    } else {
        if (qtr == 0) {
            uint4 o;
            o.x = h2u(__floats2half2_rn(v0, v1));
            o.y = h2u(__floats2half2_rn(v2, v3));
            o.z = h2u(__floats2half2_rn(v4, v5));
            o.w = h2u(__floats2half2_rn(v6, v7));
            reinterpret_cast<uint4*>(g_ahi)[w * 8 + og] = o;
        }
    }
}

// ---------------- GEMM2: g_gh2 = dinv * (A @ W2) ----------------------------
// A f16 direct LDG; W2-hi staged; per-nt streamed accumulators (low regs).
#define P2 36
__global__ __launch_bounds__(256) void gemm2_kernel(const float* __restrict__ W, int n)
{
    __shared__ unsigned Ws[64][P2];     // W hi plane

    const int tid = threadIdx.x;
    const int wid = tid >> 5, lane = tid & 31;
    const int g = lane >> 2, t = lane & 3;
    const int blockRow = blockIdx.x * 128;
    const int wr = wid * 16;

    const int r0 = blockRow + wr + g, r1 = r0 + 8;
    const bool val0 = r0 < n, val1 = r1 < n;
    unsigned a[4][4];
#pragma unroll
    for (int ks = 0; ks < 4; ks++) {
        int kb = ks * 8;
        a[ks][0] = val0 ? g_ahi[r0 * 32 + t + kb]     : 0u;
        a[ks][1] = val1 ? g_ahi[r1 * 32 + t + kb]     : 0u;
        a[ks][2] = val0 ? g_ahi[r0 * 32 + t + 4 + kb] : 0u;
        a[ks][3] = val1 ? g_ahi[r1 * 32 + t + 4 + kb] : 0u;
    }

    {
        int nn = tid & 63;
        int k2b = (tid >> 6) * 8;
#pragma unroll
        for (int j = 0; j < 8; j++) {
            int k2 = k2b + j;
            float w0 = W[(size_t)(2 * k2) * 64 + nn];
            float w1 = W[(size_t)(2 * k2 + 1) * 64 + nn];
            Ws[nn][k2] = h2u(__floats2half2_rn(w0, w1));
        }
    }
    __syncthreads();

    float dv0 = val0 ? g_dinv[r0] : 0.f;
    float dv1 = val1 ? g_dinv[r1] : 0.f;
#pragma unroll
    for (int nt = 0; nt < 8; nt++) {
        float c4[4] = {0.f, 0.f, 0.f, 0.f};
#pragma unroll
        for (int ks = 0; ks < 4; ks++) {
            int kb = ks * 8;
            unsigned b0 = Ws[nt * 8 + g][t + kb], b1 = Ws[nt * 8 + g][t + 4 + kb];
            MMA16816(c4, a[ks][0], a[ks][1], a[ks][2], a[ks][3], b0, b1);
        }
        if (val0) g_gh2[r0 * 32 + nt * 4 + t] = __floats2half2_rn(c4[0] * dv0, c4[1] * dv0);
        if (val1) g_gh2[r1 * 32 + nt * 4 + t] = __floats2half2_rn(c4[2] * dv1, c4[3] * dv1);
    }
}

// ---------------- launch ----------------------------------------------------
extern "C" void kernel_launch(void* const* d_in, const int* in_sizes, int n_in,
                              void* d_out, int out_size)
{
    const float* x  = (const float*)d_in[0];
    const int*   ei = (const int*)d_in[1];
    const float* W1 = (const float*)d_in[2];
    const float* b1 = (const float*)d_in[3];
    const float* W2 = (const float*)d_in[4];
    const float* b2 = (const float*)d_in[5];
    const float* Wc = (const float*)d_in[6];
    const float* bc = (const float*)d_in[7];
    float* out = (float*)d_out;

    const int n = in_sizes[0] / FIN;
    const int e = in_sizes[1] / 2;
    const int* src = ei;
    const int* dst = ei + e;

    void* pcnt;
    cudaGetSymbolAddress(&pcnt, g_cnt);
    cudaMemsetAsync(pcnt, 0, (size_t)n * sizeof(int));

    const int gb = (n + 127) / 128;
    mega1<<<3 * gb, 256>>>(x, W1, src, dst, n, e);

    k_scale<<<(n * 16 + 255) / 256, 256>>>(n);

    agg_kernel<1, false><<<(n + 7) / 8, 256>>>(b1, nullptr, nullptr, nullptr, n);
    gemm2_kernel<<<(n + 127) / 128, 256>>>(W2, n);
    agg_kernel<2, true><<<(n + 7) / 8, 256>>>(b2, Wc, bc, out, n);
}

// round 17
// speedup vs baseline: 1.2494x; 1.2494x over previous
#include <cuda_runtime.h>
#include <cuda_fp16.h>
#include <math.h>

#define NMAX 100000
#define EMAX 1600000
#define FIN  128
#define HID  64
#define ELLCAP 64

// ---------------- scratch (device globals: no allocation allowed) ----------
__device__ __half2  g_gh [NMAX * 32];   // layer-1 messages (dinv-prescaled after k_scale)
__device__ __half2  g_gh2[NMAX * 32];   // layer-2 messages (dinv-prescaled)
__device__ unsigned g_ahi[NMAX * 32];   // agg1 out, f16 (GEMM2 A)
__device__ float    g_dinv[NMAX];
__device__ int      g_cnt[NMAX];
__device__ int      g_ell[(size_t)NMAX * ELLCAP];   // BYTE OFFSETS (src*128)

// ---------------- helpers ---------------------------------------------------
__device__ __forceinline__ unsigned h2u(__half2 h) {
    return *reinterpret_cast<unsigned*>(&h);
}
__device__ __forceinline__ __half2 u2h(unsigned u) {
    return *reinterpret_cast<__half2*>(&u);
}
__device__ __forceinline__ float2 u2f(unsigned u) {
    return __half22float2(u2h(u));
}

#define MMA16816(c, a0, a1, a2, a3, b0, b1)                                      \
    asm volatile("mma.sync.aligned.m16n8k16.row.col.f32.f16.f16.f32 "            \
                 "{%0,%1,%2,%3},{%4,%5,%6,%7},{%8,%9},{%0,%1,%2,%3};"            \
                 : "+f"(c[0]), "+f"(c[1]), "+f"(c[2]), "+f"(c[3])                \
                 : "r"(a0), "r"(a1), "r"(a2), "r"(a3), "r"(b0), "r"(b1))

// ---------------- mega kernel: ELL scatter 2:1 interleaved with GEMM1 ------
__global__ __launch_bounds__(256) void mega1(
    const float* __restrict__ x, const float* __restrict__ W,
    const int* __restrict__ src, const int* __restrict__ dst,
    int n, int e)
{
    __shared__ unsigned As[128][20];       // A hi plane
    __shared__ unsigned Ws[64][20];        // W hi plane

    const int tid = threadIdx.x;
    const int q = blockIdx.x / 3, r = blockIdx.x % 3;

    if (r < 2) {
        int sidx = 2 * q + r;
        int base = (sidx * 256 + tid) * 4;
        if (base + 4 <= e) {
            int4 d4 = *reinterpret_cast<const int4*>(dst + base);
            int4 s4 = *reinterpret_cast<const int4*>(src + base);
            int p;
            p = atomicAdd(&g_cnt[d4.x], 1); if (p < ELLCAP) g_ell[(size_t)d4.x * ELLCAP + p] = s4.x << 7;
            p = atomicAdd(&g_cnt[d4.y], 1); if (p < ELLCAP) g_ell[(size_t)d4.y * ELLCAP + p] = s4.y << 7;
            p = atomicAdd(&g_cnt[d4.z], 1); if (p < ELLCAP) g_ell[(size_t)d4.z * ELLCAP + p] = s4.z << 7;
            p = atomicAdd(&g_cnt[d4.w], 1); if (p < ELLCAP) g_ell[(size_t)d4.w * ELLCAP + p] = s4.w << 7;
        } else {
            for (int i = base; i < e; i++) {
                int d = dst[i];
                int p = atomicAdd(&g_cnt[d], 1);
                if (p < ELLCAP) g_ell[(size_t)d * ELLCAP + p] = src[i] << 7;
            }
        }
        return;
    }

    // GEMM1: 128x64 tile, single plane (A-hi f16 x W-hi f16)
    const int wid = tid >> 5, lane = tid & 31;
    const int g = lane >> 2, t = lane & 3;
    const int blockRow = q * 128;
    const int wr = wid * 16;

    float c[8][4];
#pragma unroll
    for (int i = 0; i < 8; i++)
#pragma unroll
        for (int j = 0; j < 4; j++) c[i][j] = 0.f;

    for (int kc = 0; kc < FIN; kc += 32) {
        {
            int nn = tid & 63;
            int k2b = (tid >> 6) * 4;
#pragma unroll
            for (int j = 0; j < 4; j++) {
                int k2 = k2b + j;
                float w0 = W[(size_t)(kc + 2 * k2) * 64 + nn];
                float w1 = W[(size_t)(kc + 2 * k2 + 1) * 64 + nn];
                Ws[nn][k2] = h2u(__floats2half2_rn(w0, w1));
            }
        }
        {
            int row = tid >> 1;
            int kh = (tid & 1) * 16;
            int grow = blockRow + row;
#pragma unroll
            for (int j = 0; j < 4; j++) {
                float4 v = make_float4(0.f, 0.f, 0.f, 0.f);
                if (grow < n)
                    v = *reinterpret_cast<const float4*>(x + (size_t)grow * FIN + kc + kh + j * 4);
                int k2 = (kh >> 1) + j * 2;
                As[row][k2]     = h2u(__floats2half2_rn(v.x, v.y));
                As[row][k2 + 1] = h2u(__floats2half2_rn(v.z, v.w));
            }
        }
        __syncthreads();

#pragma unroll
        for (int ks = 0; ks < 2; ks++) {
            const int kb = ks * 8;
            unsigned a0 = As[wr + g][t + kb],     a1 = As[wr + g + 8][t + kb];
            unsigned a2 = As[wr + g][t + 4 + kb], a3 = As[wr + g + 8][t + 4 + kb];
#pragma unroll
            for (int nt = 0; nt < 8; nt++) {
                unsigned b0 = Ws[nt * 8 + g][t + kb], b1 = Ws[nt * 8 + g][t + 4 + kb];
                MMA16816(c[nt], a0, a1, a2, a3, b0, b1);
            }
        }
        __syncthreads();
    }

    int r0 = blockRow + wr + g, r1 = r0 + 8;
#pragma unroll
    for (int nt = 0; nt < 8; nt++) {
        if (r0 < n) g_gh[r0 * 32 + nt * 4 + t] = __floats2half2_rn(c[nt][0], c[nt][1]);
        if (r1 < n) g_gh[r1 * 32 + nt * 4 + t] = __floats2half2_rn(c[nt][2], c[nt][3]);
    }
}

// ---------------- k_scale: dinv = rsqrt(cnt+1); g_gh *= dinv[row] ----------
__global__ __launch_bounds__(256) void k_scale(int n) {
    int i = blockIdx.x * 256 + threadIdx.x;      // uint2 index
    if (i >= n * 16) return;
    int row = i >> 4;
    float dv = rsqrtf((float)g_cnt[row] + 1.0f);
    if ((i & 15) == 0) g_dinv[row] = dv;
    __half2* p = g_gh + 2 * i;
    float2 f0 = __half22float2(p[0]);
    float2 f1 = __half22float2(p[1]);
    p[0] = __floats2half2_rn(f0.x * dv, f0.y * dv);
    p[1] = __floats2half2_rn(f1.x * dv, f1.y * dv);
}

// ---------------- gather: half-warp LDG.64 streams, byte-offset ELL --------
__device__ __forceinline__ void gather64(
    const char* __restrict__ ghb, int w, int half, int cg, int lane,
    float2& accA, float2& accB)
{
    const char* basep = ghb + cg * 8;
    accA = make_float2(0.f, 0.f);
    accB = make_float2(0.f, 0.f);
    if (half == 0) {                         // self-loop once
        uint2 v = *reinterpret_cast<const uint2*>(basep + ((size_t)w << 7));
        accA = u2f(v.x); accB = u2f(v.y);
    }

    int m = __ldg(&g_cnt[w]); if (m > ELLCAP) m = ELLCAP;
    const int* row = g_ell + (size_t)w * ELLCAP;
    int myoff = (lane < m) ? row[lane] : 0;

    if (m > 32) {                            // rare tail, half 0 only
        if (half == 0) {
            for (int j = 32; j < m; j++) {
                uint2 v = *reinterpret_cast<const uint2*>(basep + (unsigned)__ldg(&row[j]));
                float2 a = u2f(v.x), b = u2f(v.y);
                accA.x += a.x; accA.y += a.y;
                accB.x += b.x; accB.y += b.y;
            }
        }
        m = 32;
    }

    int j = 0;
    for (; j + 16 <= m; j += 16) {
        int s[8];
#pragma unroll
        for (int q = 0; q < 8; q++) s[q] = __shfl_sync(0xffffffffu, myoff, j + 2 * q + half);
        uint2 v[8];
#pragma unroll
        for (int q = 0; q < 8; q++) v[q] = *reinterpret_cast<const uint2*>(basep + (unsigned)s[q]);
        __half2 x01 = __hadd2(u2h(v[0].x), u2h(v[1].x)), x23 = __hadd2(u2h(v[2].x), u2h(v[3].x));
        __half2 x45 = __hadd2(u2h(v[4].x), u2h(v[5].x)), x67 = __hadd2(u2h(v[6].x), u2h(v[7].x));
        __half2 y01 = __hadd2(u2h(v[0].y), u2h(v[1].y)), y23 = __hadd2(u2h(v[2].y), u2h(v[3].y));
        __half2 y45 = __hadd2(u2h(v[4].y), u2h(v[5].y)), y67 = __hadd2(u2h(v[6].y), u2h(v[7].y));
        __half2 xs = __hadd2(__hadd2(x01, x23), __hadd2(x45, x67));
        __half2 ys = __hadd2(__hadd2(y01, y23), __hadd2(y45, y67));
        float2 fx = __half22float2(xs), fy = __half22float2(ys);
        accA.x += fx.x; accA.y += fx.y;
        accB.x += fy.x; accB.y += fy.y;
    }
    if (j + 8 <= m) {
        int s[4];
#pragma unroll
        for (int q = 0; q < 4; q++) s[q] = __shfl_sync(0xffffffffu, myoff, j + 2 * q + half);
        uint2 v[4];
#pragma unroll
        for (int q = 0; q < 4; q++) v[q] = *reinterpret_cast<const uint2*>(basep + (unsigned)s[q]);
        __half2 xs = __hadd2(__hadd2(u2h(v[0].x), u2h(v[1].x)), __hadd2(u2h(v[2].x), u2h(v[3].x)));
        __half2 ys = __hadd2(__hadd2(u2h(v[0].y), u2h(v[1].y)), __hadd2(u2h(v[2].y), u2h(v[3].y)));
        float2 fx = __half22float2(xs), fy = __half22float2(ys);
        accA.x += fx.x; accA.y += fx.y;
        accB.x += fy.x; accB.y += fy.y;
        j += 8;
    }
    for (; j + 2 <= m; j += 2) {
        int s = __shfl_sync(0xffffffffu, myoff, j + half);
        uint2 v = *reinterpret_cast<const uint2*>(basep + (unsigned)s);
        float2 a = u2f(v.x), b = u2f(v.y);
        accA.x += a.x; accA.y += a.y;
        accB.x += b.x; accB.y += b.y;
    }
    if (j < m) {
        int s = __shfl_sync(0xffffffffu, myoff, j);
        uint2 v = *reinterpret_cast<const uint2*>(basep + (unsigned)s);
        if (half == 0) {
            float2 a = u2f(v.x), b = u2f(v.y);
            accA.x += a.x; accA.y += a.y;
            accB.x += b.x; accB.y += b.y;
        }
    }
}

// ---------------- aggregation: one warp per node ----------------------------
template <int LAYER, bool FINAL>
__global__ __launch_bounds__(256) void agg_kernel(
    const float* __restrict__ bias, const float* __restrict__ Wc,
    const float* __restrict__ bc, float* __restrict__ out, int n)
{
    const char* __restrict__ ghb =
        reinterpret_cast<const char*>(LAYER == 1 ? g_gh : g_gh2);

    int w = (int)((blockIdx.x * 256 + threadIdx.x) >> 5);
    int l = threadIdx.x & 31;
    if (w >= n) return;
    const int half = l >> 4, cg = l & 15;

    float2 accA, accB;
    gather64(ghb, w, half, cg, l, accA, accB);

    accA.x += __shfl_xor_sync(0xffffffffu, accA.x, 16);
    accA.y += __shfl_xor_sync(0xffffffffu, accA.y, 16);
    accB.x += __shfl_xor_sync(0xffffffffu, accB.x, 16);
    accB.y += __shfl_xor_sync(0xffffffffu, accB.y, 16);

    float dv = g_dinv[w];
    float4 bb = reinterpret_cast<const float4*>(bias)[cg];
    float v0 = fmaxf(fmaf(dv, accA.x, bb.x), 0.f);
    float v1 = fmaxf(fmaf(dv, accA.y, bb.y), 0.f);
    float v2 = fmaxf(fmaf(dv, accB.x, bb.z), 0.f);
    float v3 = fmaxf(fmaf(dv, accB.y, bb.w), 0.f);

    if (FINAL) {
        float4 wc = reinterpret_cast<const float4*>(Wc)[cg];
        float p = fmaf(v0, wc.x, fmaf(v1, wc.y, fmaf(v2, wc.z, v3 * wc.w)));
#pragma unroll
        for (int off = 8; off; off >>= 1) p += __shfl_xor_sync(0xffffffffu, p, off);
        if (l == 0) out[w] = p + bc[0];
    } else {
        if (half == 0) {
            uint2 o;
            o.x = h2u(__floats2half2_rn(v0, v1));
            o.y = h2u(__floats2half2_rn(v2, v3));
            reinterpret_cast<uint2*>(g_ahi)[w * 16 + cg] = o;
        }
    }
}

// ---------------- GEMM2: g_gh2 = dinv * (A @ W2) ----------------------------
// A f16 direct LDG; W2-hi staged; per-nt streamed accumulators (regs ~34).
#define P2 36
__global__ __launch_bounds__(256) void gemm2_kernel(const float* __restrict__ W, int n)
{
    __shared__ unsigned Ws[64][P2];     // W hi plane

    const int tid = threadIdx.x;
    const int wid = tid >> 5, lane = tid & 31;
    const int g = lane >> 2, t = lane & 3;
    const int blockRow = blockIdx.x * 128;
    const int wr = wid * 16;

    const int r0 = blockRow + wr + g, r1 = r0 + 8;
    const bool val0 = r0 < n, val1 = r1 < n;
    unsigned a[4][4];
#pragma unroll
    for (int ks = 0; ks < 4; ks++) {
        int kb = ks * 8;
        a[ks][0] = val0 ? g_ahi[r0 * 32 + t + kb]     : 0u;
        a[ks][1] = val1 ? g_ahi[r1 * 32 + t + kb]     : 0u;
        a[ks][2] = val0 ? g_ahi[r0 * 32 + t + 4 + kb] : 0u;
        a[ks][3] = val1 ? g_ahi[r1 * 32 + t + 4 + kb] : 0u;
    }

    {
        int nn = tid & 63;
        int k2b = (tid >> 6) * 8;
#pragma unroll
        for (int j = 0; j < 8; j++) {
            int k2 = k2b + j;
            float w0 = W[(size_t)(2 * k2) * 64 + nn];
            float w1 = W[(size_t)(2 * k2 + 1) * 64 + nn];
            Ws[nn][k2] = h2u(__floats2half2_rn(w0, w1));
        }
    }
    __syncthreads();

    float dv0 = val0 ? g_dinv[r0] : 0.f;
    float dv1 = val1 ? g_dinv[r1] : 0.f;
#pragma unroll
    for (int nt = 0; nt < 8; nt++) {
        float c4[4] = {0.f, 0.f, 0.f, 0.f};
#pragma unroll
        for (int ks = 0; ks < 4; ks++) {
            int kb = ks * 8;
            unsigned b0 = Ws[nt * 8 + g][t + kb], b1 = Ws[nt * 8 + g][t + 4 + kb];
            MMA16816(c4, a[ks][0], a[ks][1], a[ks][2], a[ks][3], b0, b1);
        }
        if (val0) g_gh2[r0 * 32 + nt * 4 + t] = __floats2half2_rn(c4[0] * dv0, c4[1] * dv0);
        if (val1) g_gh2[r1 * 32 + nt * 4 + t] = __floats2half2_rn(c4[2] * dv1, c4[3] * dv1);
    }
}

// ---------------- launch ----------------------------------------------------
extern "C" void kernel_launch(void* const* d_in, const int* in_sizes, int n_in,
                              void* d_out, int out_size)
{
    const float* x  = (const float*)d_in[0];
    const int*   ei = (const int*)d_in[1];
    const float* W1 = (const float*)d_in[2];
    const float* b1 = (const float*)d_in[3];
    const float* W2 = (const float*)d_in[4];
    const float* b2 = (const float*)d_in[5];
    const float* Wc = (const float*)d_in[6];
    const float* bc = (const float*)d_in[7];
    float* out = (float*)d_out;

    const int n = in_sizes[0] / FIN;
    const int e = in_sizes[1] / 2;
    const int* src = ei;
    const int* dst = ei + e;

    void* pcnt;
    cudaGetSymbolAddress(&pcnt, g_cnt);
    cudaMemsetAsync(pcnt, 0, (size_t)n * sizeof(int));

    const int gb = (n + 127) / 128;
    mega1<<<3 * gb, 256>>>(x, W1, src, dst, n, e);

    k_scale<<<(n * 16 + 255) / 256, 256>>>(n);

    agg_kernel<1, false><<<(n + 7) / 8, 256>>>(b1, nullptr, nullptr, nullptr, n);
    gemm2_kernel<<<(n + 127) / 128, 256>>>(W2, n);
    agg_kernel<2, true><<<(n + 7) / 8, 256>>>(b2, Wc, bc, out, n);
}